// round 5
// baseline (speedup 1.0000x reference)
#include <cuda_runtime.h>

#define HW       64
#define CH       3
#define NPIX     (HW * HW)              // 4096
#define NELEM    (NPIX * CH)            // 12288 floats per image
#define NIMG     512
#define CROWS    8                      // rows per chunk
#define CPI      (HW / CROWS)           // 8 chunks per image
#define NCHUNK   (NIMG * CPI)           // 4096 chunks
#define CPIX     (CROWS * HW)           // 512 pixels per chunk
#define T_A      256
#define PPT_A    (CPIX / T_A)           // 2 pixels/thread/chunk
#define GRID_A   888                    // 6 * 148
#define BROWS    (CROWS + 2)            // staged rows incl. halo
#define SMEM_A   (BROWS * HW * 16 + 128)
#define T_B      256
#define LOG2E    1.4426950408889634f

__device__ float2 g_part[NCHUNK];       // per-chunk (sum_noise, sum_detail)

__device__ __forceinline__ float ex2f(float x) {
    float r; asm("ex2.approx.ftz.f32 %0, %1;" : "=f"(r) : "f"(x)); return r;
}
__device__ __forceinline__ float rcpf(float x) {
    float r; asm("rcp.approx.ftz.f32 %0, %1;" : "=f"(r) : "f"(x)); return r;
}

// ---------------------------------------------------------------- kernel A
__global__ void __launch_bounds__(T_A, 6)
dnsA_kernel(const float* __restrict__ images,
            const float* __restrict__ params,
            const float* __restrict__ kptr,
            float* __restrict__ out)
{
    extern __shared__ float smem[];
    float*  red  = smem;                 // 32 floats scratch
    float*  buf  = smem + 32;            // BROWS*HW float4
    float4* buf4 = (float4*)buf;

    const int tid = threadIdx.x;
    const float k_raw = *kptr;

    for (int g = blockIdx.x; g < NCHUNK; g += GRID_A) {
        const int img   = g >> 3;
        const int crow0 = (g & 7) * CROWS;
        const float* base = images + (size_t)img * NELEM;
        float*       dst  = out    + (size_t)img * NELEM;

        // ---- stage BROWS rows (reflect halo) into padded float4 smem ----
        #pragma unroll
        for (int it = 0; it < 2; ++it) {
            const int f = tid + it * T_A;             // 0..511, need 480
            if (f < BROWS * 48) {
                const int row  = f / 48;
                const int col4 = f - row * 48;
                int srow = crow0 + row - 1;
                srow = abs(srow);                      // -1 -> 1
                srow = 63 - abs(63 - srow);            // 64 -> 62
                const float4 v = ((const float4*)(base + srow * (HW * CH)))[col4];
                const float  w[4] = { v.x, v.y, v.z, v.w };
                const int wbase = col4 * 4;
                #pragma unroll
                for (int k = 0; k < 4; ++k) {
                    const int widx = wbase + k;
                    const int pix  = widx / 3;
                    const int ch   = widx - pix * 3;
                    buf[(row * HW + pix) * 4 + ch] = w[k];
                }
            }
        }

        // ---- per-image parameters (uniform across block, cached in L2) ----
        const float* p = params + img * 7;
        const float sigma_s = fminf(fmaxf(p[0], 0.2f), 5.0f);
        const float sigma_r = fminf(fmaxf(p[1], 0.01f), 1.0f);
        const float sigma_f = fminf(fmaxf(p[2], 0.2f), 3.0f);
        const float lam     = fminf(fmaxf(p[3], 0.1f), 2.0f);
        const float tau     = fminf(fmaxf(p[4], 0.5f), 5.0f);
        const float gain    = fminf(fmaxf(p[5], 0.2f), 2.0f);
        const float offset  = fminf(fmaxf(p[6], 0.01f), 1.0f);
        const float k_pos   = fmaxf(fabsf(k_raw), 1.0f);

        const float ls2      = (-0.5f / (sigma_s * sigma_s)) * LOG2E;
        const float b_edge   = ls2;
        const float b_corner = 2.0f * ls2;
        const float cR       = (-0.5f / (sigma_r * sigma_r)) * LOG2E;

        const float ef   = __expf(-0.5f / (sigma_f * sigma_f));
        const float ef2  = ef * ef;
        const float ifn  = rcpf(1.0f + 2.0f * ef);
        const float ifn2 = ifn * ifn;

        const float invtau2L2 = rcpf(tau * tau) * LOG2E;
        const float kL2       = k_pos * LOG2E;

        __syncthreads();

        float sum_noise = 0.0f, sum_det = 0.0f;

        #pragma unroll
        for (int i = 0; i < PPT_A; ++i) {
            const int lp = tid + i * T_A;             // 0..511 in chunk
            const int ly = lp >> 6, x = lp & 63;
            const int br = ly + 1;                    // buffer row of center
            const int xm = abs(x - 1);
            const int xp = 63 - abs(62 - x);
            const int r0 = br * HW, rm = r0 - HW, rp = r0 + HW;

            const float4 C = buf4[r0 + x];

            float bn0 = C.x, bn1 = C.y, bn2 = C.z, bden = 1.0f;
            float e40 = 0.f, e41 = 0.f, e42 = 0.f;
            float c40 = 0.f, c41 = 0.f, c42 = 0.f;

            #define TAP(IDX, BIAS, A0, A1, A2)                                 \
            {                                                                  \
                const float4 t = buf4[IDX];                                    \
                const float d0 = t.x - C.x, d1 = t.y - C.y, d2 = t.z - C.z;    \
                const float cds = d0 * d0 + d1 * d1 + d2 * d2;                 \
                const float kk = ex2f(fmaf(cds, cR, BIAS));                    \
                bden += kk;                                                    \
                bn0 = fmaf(kk, t.x, bn0);                                      \
                bn1 = fmaf(kk, t.y, bn1);                                      \
                bn2 = fmaf(kk, t.z, bn2);                                      \
                A0 += t.x; A1 += t.y; A2 += t.z;                               \
            }
            TAP(rm + x,  b_edge,   e40, e41, e42)
            TAP(rp + x,  b_edge,   e40, e41, e42)
            TAP(r0 + xm, b_edge,   e40, e41, e42)
            TAP(r0 + xp, b_edge,   e40, e41, e42)
            TAP(rm + xm, b_corner, c40, c41, c42)
            TAP(rm + xp, b_corner, c40, c41, c42)
            TAP(rp + xm, b_corner, c40, c41, c42)
            TAP(rp + xp, b_corner, c40, c41, c42)
            #undef TAP

            const float inv_den = rcpf(bden);
            const float cen[3]  = { C.x, C.y, C.z };
            const float bnum[3] = { bn0, bn1, bn2 };
            const float gr[3]   = { fmaf(ef, e40, fmaf(ef2, c40, C.x)),
                                    fmaf(ef, e41, fmaf(ef2, c41, C.y)),
                                    fmaf(ef, e42, fmaf(ef2, c42, C.z)) };
            const int obase = ((crow0 + ly) * HW + x) * 3;
            #pragma unroll
            for (int c = 0; c < CH; ++c) {
                const float bf     = bnum[c] * inv_den;
                const float detail = fmaf(-ifn2, gr[c], cen[c]);
                const float ad     = fabsf(detail);
                const float denom  = fmaxf(cen[c] + offset, 1e-5f);
                const float ne     = fminf(ad * gain * rcpf(denom), 10.0f);
                sum_noise += ne;
                sum_det   += ad;
                const float em    = ex2f(-(ne * ne) * invtau2L2);
                const float t1    = 1.0f - em;
                const float nmask = t1 * t1;
                const float dmask = rcpf(1.0f + ex2f(-kL2 * (ad - 0.002f)));
                const float v     = fmaf(lam * detail, nmask * dmask, bf);
                dst[obase + c] = fminf(fmaxf(v, 1e-5f), 1.0f);
            }
        }

        // ---- per-chunk reduction -> g_part[g] (deterministic) ----
        #pragma unroll
        for (int o = 16; o > 0; o >>= 1) {
            sum_noise += __shfl_xor_sync(0xFFFFFFFFu, sum_noise, o);
            sum_det   += __shfl_xor_sync(0xFFFFFFFFu, sum_det, o);
        }
        if ((tid & 31) == 0) {
            red[tid >> 5]     = sum_noise;        // 8 warps
            red[8 + (tid >> 5)] = sum_det;
        }
        __syncthreads();
        if (tid == 0) {
            float tn = 0.f, td = 0.f;
            #pragma unroll
            for (int w = 0; w < T_A / 32; ++w) { tn += red[w]; td += red[8 + w]; }
            g_part[g] = make_float2(tn, td);
        }
        // red[] reuse is safe: next write to red happens only after the next
        // __syncthreads() above, which tid 0 reaches after its reads.
    }
}

// ---------------------------------------------------------------- kernel B
__global__ void __launch_bounds__(T_B)
dnsB_kernel(const float* __restrict__ images,
            float* __restrict__ out)
{
    const int img = blockIdx.x;
    float tn = 0.f, td = 0.f;
    #pragma unroll
    for (int i = 0; i < CPI; ++i) {
        const float2 s = g_part[img * CPI + i];
        tn += s.x; td += s.y;
    }
    const float inv_n = 1.0f / (float)NELEM;
    if (!((tn * inv_n < 1e-4f) || (td * inv_n < 1e-4f))) return;

    // rare skip path: out = clip(x)
    const float4* s4 = (const float4*)(images + (size_t)img * NELEM);
    float4*       d4 = (float4*)(out + (size_t)img * NELEM);
    const int tid = threadIdx.x;
    #pragma unroll
    for (int i = 0; i < (NELEM / 4) / T_B; ++i) {
        float4 v = s4[tid + i * T_B];
        v.x = fminf(fmaxf(v.x, 1e-5f), 1.0f);
        v.y = fminf(fmaxf(v.y, 1e-5f), 1.0f);
        v.z = fminf(fmaxf(v.z, 1e-5f), 1.0f);
        v.w = fminf(fmaxf(v.w, 1e-5f), 1.0f);
        d4[tid + i * T_B] = v;
    }
}

extern "C" void kernel_launch(void* const* d_in, const int* in_sizes, int n_in,
                              void* d_out, int out_size)
{
    const float* images = (const float*)d_in[0];
    const float* params = (const float*)d_in[1];
    const float* kptr   = (const float*)d_in[2];
    float*       out    = (float*)d_out;

    cudaFuncSetAttribute(dnsA_kernel,
                         cudaFuncAttributeMaxDynamicSharedMemorySize, SMEM_A);
    dnsA_kernel<<<GRID_A, T_A, SMEM_A>>>(images, params, kptr, out);
    dnsB_kernel<<<NIMG, T_B>>>(images, out);
}